// round 5
// baseline (speedup 1.0000x reference)
#include <cuda_runtime.h>
#include <cstdint>

#define BB 32
#define LL 128
#define FF 128
#define RR 4096
#define NITEMS 262144
#define CAP 32

// Scratch (device globals; no allocation allowed)
__device__ int g_count[BB * RR];           // 512 KB (memset to 0 each launch)
__device__ int g_bucket[BB * RR * CAP];    // 16 MB, entry = (slot<<18)|item

// ---------------------------------------------------------------------------
// Bucketize items by (batch, role), 4 items per thread via int4 loads.
// ---------------------------------------------------------------------------
__device__ __forceinline__ void put_item(int b, int s, int r, int item) {
    int bkt = b * RR + r;
    int pos = atomicAdd(&g_count[bkt], 1);
    if (pos < CAP) g_bucket[bkt * CAP + pos] = (s << 18) | item;
}

__global__ void build_buckets_kernel(const int4* __restrict__ batch_idx,
                                     const int4* __restrict__ slot_idx,
                                     const int4* __restrict__ role_idx) {
    int t = blockIdx.x * blockDim.x + threadIdx.x;
    if (t >= NITEMS / 4) return;
    int4 b4 = batch_idx[t];
    int4 s4 = slot_idx[t];
    int4 r4 = role_idx[t];
    int item = t << 2;
    put_item(b4.x, s4.x, r4.x, item + 0);
    put_item(b4.y, s4.y, r4.y, item + 1);
    put_item(b4.z, s4.z, r4.z, item + 2);
    put_item(b4.w, s4.w, r4.w, item + 3);
}

// ---------------------------------------------------------------------------
// Gather. Each warp owns rows {2k, 2k+1, 2k+2048, 2k+2049} of batch b.
// Buckets (bid):
//   0: cons role k        -> w2*od2 to a0 (row 2k),   w3*od2 to a1 (row 2k+1)
//   1: cons role k+1024   -> w2*od2 to b0,            w3*od2 to b1
//   2: car  role 4k       -> w0*od0 to a0
//   3: cdr  role 4k+1     -> w1*od1 to a0   (count forced 0 when k==0)
//   4: car  role 4k+2     -> w0*od0 to a1
//   5: cdr  role 4k+3     -> w1*od1 to a1
// All buckets flattened into one worklist; depth-4 prefetch pipeline.
// ---------------------------------------------------------------------------
__global__ void __launch_bounds__(256) gather_kernel(
    const float* __restrict__ mem,       // (N, F)
    const float* __restrict__ arg_w,     // (B, L, 4)
    const float* __restrict__ root,      // (B, F)
    const float* __restrict__ op_dist,   // (B, 3)
    float* __restrict__ out)             // (B, R, F)
{
    const unsigned FULL = 0xffffffffu;
    int w = blockIdx.x * (blockDim.x >> 5) + (threadIdx.x >> 5);
    if (w >= BB * 1024) return;
    const int lane = threadIdx.x & 31;
    const int b = w >> 10;
    const int k = w & 1023;
    const int base = b * RR;

    const float od0 = op_dist[b * 3 + 0];
    const float od1 = op_dist[b * 3 + 1];
    const float od2 = op_dist[b * 3 + 2];
    const float* awb = arg_w + (size_t)b * LL * 4;

    // counts for the 6 buckets
    int4 c4 = *(const int4*)&g_count[base + 4 * k];   // bids 2..5
    int ch  = g_count[base + k];                      // bid 0
    int cl  = g_count[base + k + 1024];               // bid 1
    int c0 = min(ch, CAP);
    int c1 = min(cl, CAP);
    int c2 = min(c4.x, CAP);
    int c3 = (k == 0) ? 0 : min(c4.y, CAP);
    int c5v = min(c4.z, CAP);
    int c6v = min(c4.w, CAP);

    // prefix sums
    int p1 = c0, p2 = p1 + c1, p3 = p2 + c2, p4 = p3 + c3, p5 = p4 + c5v;
    int T = p5 + c6v;

    float4 a0 = make_float4(0.f, 0.f, 0.f, 0.f);
    float4 a1 = make_float4(0.f, 0.f, 0.f, 0.f);
    float4 b0 = make_float4(0.f, 0.f, 0.f, 0.f);
    float4 b1 = make_float4(0.f, 0.f, 0.f, 0.f);

    for (int cs = 0; cs < T; cs += 32) {
        int n = min(T - cs, 32);
        // lane j: locate (bucket, pos) of global item cs+lane, fetch packed entry
        int j = cs + lane;
        int bid = (j >= p1) + (j >= p2) + (j >= p3) + (j >= p4) + (j >= p5);
        int start = 0, bk = base + k;
        if (bid == 1) { start = p1; bk = base + k + 1024; }
        if (bid == 2) { start = p2; bk = base + 4 * k; }
        if (bid == 3) { start = p3; bk = base + 4 * k + 1; }
        if (bid == 4) { start = p4; bk = base + 4 * k + 2; }
        if (bid == 5) { start = p5; bk = base + 4 * k + 3; }
        int pk = 0;
        if (j < T) pk = g_bucket[bk * CAP + (j - start)] | (bid << 25);

        // depth-4 prefetch pipeline over this chunk's n items
        int eq[4]; float4 mq[4];
#pragma unroll
        for (int u = 0; u < 4; u++) {
            if (u < n) {
                int e = __shfl_sync(FULL, pk, u);
                eq[u] = e;
                mq[u] = ((const float4*)(mem + (size_t)(e & 0x3FFFF) * FF))[lane];
            }
        }
        for (int tb = 0; tb < n; tb += 4) {
#pragma unroll
            for (int u = 0; u < 4; u++) {
                int t = tb + u;
                if (t < n) {
                    int e = eq[u];
                    float4 m = mq[u];
                    int tn = t + 4;
                    if (tn < n) {            // prefetch into this slot
                        int e2 = __shfl_sync(FULL, pk, tn);
                        eq[u] = e2;
                        mq[u] = ((const float4*)(mem + (size_t)(e2 & 0x3FFFF) * FF))[lane];
                    }
                    int slot = (e >> 18) & 127;
                    unsigned ebid = ((unsigned)e) >> 25;
                    float4 w4 = *(const float4*)(awb + (slot << 2));
                    if (ebid == 0) {
                        float ce = od2 * w4.z, co = od2 * w4.w;
                        a0.x += ce * m.x; a0.y += ce * m.y; a0.z += ce * m.z; a0.w += ce * m.w;
                        a1.x += co * m.x; a1.y += co * m.y; a1.z += co * m.z; a1.w += co * m.w;
                    } else if (ebid == 1) {
                        float ce = od2 * w4.z, co = od2 * w4.w;
                        b0.x += ce * m.x; b0.y += ce * m.y; b0.z += ce * m.z; b0.w += ce * m.w;
                        b1.x += co * m.x; b1.y += co * m.y; b1.z += co * m.z; b1.w += co * m.w;
                    } else if (ebid == 2) {
                        float c = od0 * w4.x;
                        a0.x += c * m.x; a0.y += c * m.y; a0.z += c * m.z; a0.w += c * m.w;
                    } else if (ebid == 3) {
                        float c = od1 * w4.y;
                        a0.x += c * m.x; a0.y += c * m.y; a0.z += c * m.z; a0.w += c * m.w;
                    } else if (ebid == 4) {
                        float c = od0 * w4.x;
                        a1.x += c * m.x; a1.y += c * m.y; a1.z += c * m.z; a1.w += c * m.w;
                    } else {
                        float c = od1 * w4.y;
                        a1.x += c * m.x; a1.y += c * m.y; a1.z += c * m.z; a1.w += c * m.w;
                    }
                }
            }
        }
    }

    if (k == 0) {   // row 1 += od2 * root_filler[b]
        float4 rf = ((const float4*)(root + (size_t)b * FF))[lane];
        a1.x += od2 * rf.x; a1.y += od2 * rf.y; a1.z += od2 * rf.z; a1.w += od2 * rf.w;
    }

    float* oh = out + ((size_t)base + 2 * (size_t)k) * FF;
    ((float4*)oh)[lane]        = a0;    // row 2k
    ((float4*)(oh + FF))[lane] = a1;    // row 2k+1
    float* ol = oh + (size_t)2048 * FF;
    ((float4*)ol)[lane]        = b0;    // row 2k+2048
    ((float4*)(ol + FF))[lane] = b1;    // row 2k+2049
}

// ---------------------------------------------------------------------------
extern "C" void kernel_launch(void* const* d_in, const int* in_sizes, int n_in,
                              void* d_out, int out_size) {
    const float* mem     = (const float*)d_in[0];
    const float* arg_w   = (const float*)d_in[1];
    const float* root    = (const float*)d_in[2];
    const float* op_dist = (const float*)d_in[3];
    const int*   batch_i = (const int*)d_in[4];
    const int*   slot_i  = (const int*)d_in[5];
    const int*   role_i  = (const int*)d_in[6];
    float* out = (float*)d_out;

    void* cnt_ptr = nullptr;
    cudaGetSymbolAddress(&cnt_ptr, g_count);
    cudaMemsetAsync(cnt_ptr, 0, sizeof(int) * BB * RR, 0);

    build_buckets_kernel<<<(NITEMS / 4 + 255) / 256, 256>>>(
        (const int4*)batch_i, (const int4*)slot_i, (const int4*)role_i);

    const int nwarps = BB * 1024;                  // 32768
    gather_kernel<<<nwarps / 8, 256>>>(mem, arg_w, root, op_dist, out);
}

// round 8
// speedup vs baseline: 1.1166x; 1.1166x over previous
#include <cuda_runtime.h>
#include <cstdint>

#define BB 32
#define LL 128
#define FF 128
#define RR 4096
#define NITEMS 262144
#define CAP 32

// Scratch (device globals; no allocation allowed)
__device__ int  g_count[BB * RR];                    // 512 KB (memset 0 per launch)
__device__ int4 g_bucket[(size_t)BB * RR * CAP];     // 64 MB: {item, cA, cConsE, cConsO}

// ---------------------------------------------------------------------------
// Build: bucketize by (batch, role) and fold ALL weight math into the entry.
//   cA     = role even ? od0*w0 : (role==1 ? 0 : od1*w1)   (car/cdr coefficient)
//   cConsE = od2*w2   (feeds even output row 2*role)
//   cConsO = od2*w3   (feeds odd  output row 2*role+1)
// ---------------------------------------------------------------------------
__device__ __forceinline__ void put_item(const float* __restrict__ arg_w,
                                         const float* __restrict__ op_dist,
                                         int b, int s, int r, int item) {
    float4 w4 = *(const float4*)(arg_w + (((b << 7) + s) << 2));
    float od0 = op_dist[b * 3 + 0];
    float od1 = op_dist[b * 3 + 1];
    float od2 = op_dist[b * 3 + 2];
    float cA = (r & 1) ? ((r == 1) ? 0.f : od1 * w4.y) : od0 * w4.x;
    int bkt = b * RR + r;
    int pos = atomicAdd(&g_count[bkt], 1);
    if (pos < CAP)
        g_bucket[(size_t)bkt * CAP + pos] =
            make_int4(item, __float_as_int(cA),
                      __float_as_int(od2 * w4.z), __float_as_int(od2 * w4.w));
}

__global__ void build_buckets_kernel(const int4* __restrict__ batch_idx,
                                     const int4* __restrict__ slot_idx,
                                     const int4* __restrict__ role_idx,
                                     const float* __restrict__ arg_w,
                                     const float* __restrict__ op_dist) {
    int t = blockIdx.x * blockDim.x + threadIdx.x;
    if (t >= NITEMS / 4) return;
    int4 b4 = batch_idx[t];
    int4 s4 = slot_idx[t];
    int4 r4 = role_idx[t];
    int item = t << 2;
    put_item(arg_w, op_dist, b4.x, s4.x, r4.x, item + 0);
    put_item(arg_w, op_dist, b4.y, s4.y, r4.y, item + 1);
    put_item(arg_w, op_dist, b4.z, s4.z, r4.z, item + 2);
    put_item(arg_w, op_dist, b4.w, s4.w, r4.w, item + 3);
}

// ---------------------------------------------------------------------------
// Gather. Warp (b,k), k in [0,1024): owns rows {2k, 2k+1, 2k+2048, 2k+2049}.
// Six buckets, processed depth-by-depth with 6 independent entry->row chains:
//   0: cons role k        -> cConsE to a0 (row 2k),  cConsO to a1 (row 2k+1)
//   1: cons role k+1024   -> cConsE to b0,           cConsO to b1
//   2: role 4k   (car)    -> cA to a0
//   3: role 4k+1 (cdr)    -> cA to a0  (cA==0 for role 1, so no special case)
//   4: role 4k+2 (car)    -> cA to a1
//   5: role 4k+3 (cdr)    -> cA to a1
// Lane l holds float4 chunk l of each 128-float row.
// ---------------------------------------------------------------------------
__global__ void __launch_bounds__(256) gather_kernel(
    const float* __restrict__ mem,       // (N, F)
    const float* __restrict__ root,      // (B, F)
    const float* __restrict__ op_dist,   // (B, 3)
    float* __restrict__ out)             // (B, R, F)
{
    int w = blockIdx.x * (blockDim.x >> 5) + (threadIdx.x >> 5);
    if (w >= BB * 1024) return;
    const int lane = threadIdx.x & 31;
    const int b = w >> 10;
    const int k = w & 1023;
    const int base = b * RR;

    // bucket ids
    const int bk0 = base + k;
    const int bk1 = base + k + 1024;
    const int bk2 = base + 4 * k;

    // counts (warp-uniform)
    int4 c4 = *(const int4*)&g_count[bk2];
    int c0 = min(g_count[bk0], CAP);
    int c1 = min(g_count[bk1], CAP);
    int c2 = min(c4.x, CAP);
    int c3 = min(c4.y, CAP);
    int c5 = min(c4.z, CAP);
    int c6 = min(c4.w, CAP);
    int maxc = max(max(max(c0, c1), max(c2, c3)), max(c5, c6));

    float4 a0 = make_float4(0.f, 0.f, 0.f, 0.f);
    float4 a1 = make_float4(0.f, 0.f, 0.f, 0.f);
    float4 b0 = make_float4(0.f, 0.f, 0.f, 0.f);
    float4 b1 = make_float4(0.f, 0.f, 0.f, 0.f);

    for (int i = 0; i < maxc; i++) {
        int4 E0, E1, E2, E3, E4, E5;
        float4 M0, M1, M2, M3, M4, M5;
        bool v0 = i < c0, v1 = i < c1, v2 = i < c2;
        bool v3 = i < c3, v4 = i < c5, v5 = i < c6;
        // six independent entry->row chains (all loads can be in flight together)
        if (v0) { E0 = g_bucket[(size_t)bk0 * CAP + i];
                  M0 = ((const float4*)(mem + (size_t)E0.x * FF))[lane]; }
        if (v1) { E1 = g_bucket[(size_t)bk1 * CAP + i];
                  M1 = ((const float4*)(mem + (size_t)E1.x * FF))[lane]; }
        if (v2) { E2 = g_bucket[((size_t)bk2 + 0) * CAP + i];
                  M2 = ((const float4*)(mem + (size_t)E2.x * FF))[lane]; }
        if (v3) { E3 = g_bucket[((size_t)bk2 + 1) * CAP + i];
                  M3 = ((const float4*)(mem + (size_t)E3.x * FF))[lane]; }
        if (v4) { E4 = g_bucket[((size_t)bk2 + 2) * CAP + i];
                  M4 = ((const float4*)(mem + (size_t)E4.x * FF))[lane]; }
        if (v5) { E5 = g_bucket[((size_t)bk2 + 3) * CAP + i];
                  M5 = ((const float4*)(mem + (size_t)E5.x * FF))[lane]; }

        if (v0) {
            float ce = __int_as_float(E0.z), co = __int_as_float(E0.w);
            a0.x += ce * M0.x; a0.y += ce * M0.y; a0.z += ce * M0.z; a0.w += ce * M0.w;
            a1.x += co * M0.x; a1.y += co * M0.y; a1.z += co * M0.z; a1.w += co * M0.w;
        }
        if (v1) {
            float ce = __int_as_float(E1.z), co = __int_as_float(E1.w);
            b0.x += ce * M1.x; b0.y += ce * M1.y; b0.z += ce * M1.z; b0.w += ce * M1.w;
            b1.x += co * M1.x; b1.y += co * M1.y; b1.z += co * M1.z; b1.w += co * M1.w;
        }
        if (v2) {
            float c = __int_as_float(E2.y);
            a0.x += c * M2.x; a0.y += c * M2.y; a0.z += c * M2.z; a0.w += c * M2.w;
        }
        if (v3) {
            float c = __int_as_float(E3.y);
            a0.x += c * M3.x; a0.y += c * M3.y; a0.z += c * M3.z; a0.w += c * M3.w;
        }
        if (v4) {
            float c = __int_as_float(E4.y);
            a1.x += c * M4.x; a1.y += c * M4.y; a1.z += c * M4.z; a1.w += c * M4.w;
        }
        if (v5) {
            float c = __int_as_float(E5.y);
            a1.x += c * M5.x; a1.y += c * M5.y; a1.z += c * M5.z; a1.w += c * M5.w;
        }
    }

    if (k == 0) {   // row 1 += od2 * root_filler[b]
        float od2 = op_dist[b * 3 + 2];
        float4 rf = ((const float4*)(root + (size_t)b * FF))[lane];
        a1.x += od2 * rf.x; a1.y += od2 * rf.y; a1.z += od2 * rf.z; a1.w += od2 * rf.w;
    }

    float* oh = out + ((size_t)base + 2 * (size_t)k) * FF;
    ((float4*)oh)[lane]        = a0;    // row 2k
    ((float4*)(oh + FF))[lane] = a1;    // row 2k+1
    float* ol = oh + (size_t)2048 * FF;
    ((float4*)ol)[lane]        = b0;    // row 2k+2048
    ((float4*)(ol + FF))[lane] = b1;    // row 2k+2049
}

// ---------------------------------------------------------------------------
extern "C" void kernel_launch(void* const* d_in, const int* in_sizes, int n_in,
                              void* d_out, int out_size) {
    const float* mem     = (const float*)d_in[0];
    const float* arg_w   = (const float*)d_in[1];
    const float* root    = (const float*)d_in[2];
    const float* op_dist = (const float*)d_in[3];
    const int*   batch_i = (const int*)d_in[4];
    const int*   slot_i  = (const int*)d_in[5];
    const int*   role_i  = (const int*)d_in[6];
    float* out = (float*)d_out;

    void* cnt_ptr = nullptr;
    cudaGetSymbolAddress(&cnt_ptr, g_count);
    cudaMemsetAsync(cnt_ptr, 0, sizeof(int) * BB * RR, 0);

    build_buckets_kernel<<<(NITEMS / 4 + 255) / 256, 256>>>(
        (const int4*)batch_i, (const int4*)slot_i, (const int4*)role_i,
        arg_w, op_dist);

    const int nwarps = BB * 1024;                  // 32768
    gather_kernel<<<nwarps / 8, 256>>>(mem, root, op_dist, out);
}

// round 9
// speedup vs baseline: 1.4450x; 1.2942x over previous
#include <cuda_runtime.h>
#include <cstdint>

#define BB 32
#define LL 128
#define FF 128
#define RR 4096
#define NITEMS 262144
#define CAP 32

// Scratch (device globals; no allocation allowed)
__device__ int g_count[BB * RR];           // 512 KB (memset 0 per launch)
__device__ int g_bucket[BB * RR * CAP];    // 16 MB, entry = (slot<<18)|item

// ---------------------------------------------------------------------------
// Bucketize items by (batch, role), 4 items per thread via int4 loads.
// ---------------------------------------------------------------------------
__device__ __forceinline__ void put_item(int b, int s, int r, int item) {
    int bkt = b * RR + r;
    int pos = atomicAdd(&g_count[bkt], 1);
    if (pos < CAP) g_bucket[bkt * CAP + pos] = (s << 18) | item;
}

__global__ void build_buckets_kernel(const int4* __restrict__ batch_idx,
                                     const int4* __restrict__ slot_idx,
                                     const int4* __restrict__ role_idx) {
    int t = blockIdx.x * blockDim.x + threadIdx.x;
    if (t >= NITEMS / 4) return;
    int4 b4 = batch_idx[t];
    int4 s4 = slot_idx[t];
    int4 r4 = role_idx[t];
    int item = t << 2;
    put_item(b4.x, s4.x, r4.x, item + 0);
    put_item(b4.y, s4.y, r4.y, item + 1);
    put_item(b4.z, s4.z, r4.z, item + 2);
    put_item(b4.w, s4.w, r4.w, item + 3);
}

// ---------------------------------------------------------------------------
// Accumulate one bucket into one accumulator.
// coefficient = coef * arg_w[b, slot, wcomp]; 2-way unrolled.
// ---------------------------------------------------------------------------
__device__ __forceinline__ void accum_one(
    const float* __restrict__ mem, const float* __restrict__ awb,
    int entry, int cnt, int lane, float coef, int wcomp, float4& acc)
{
    int i = 0;
    for (; i + 1 < cnt; i += 2) {
        int e0 = __shfl_sync(0xffffffffu, entry, i);
        int e1 = __shfl_sync(0xffffffffu, entry, i + 1);
        float w0 = awb[((e0 >> 18) << 2) + wcomp];
        float w1 = awb[((e1 >> 18) << 2) + wcomp];
        float4 m0 = ((const float4*)(mem + (size_t)(e0 & 0x3FFFF) * FF))[lane];
        float4 m1 = ((const float4*)(mem + (size_t)(e1 & 0x3FFFF) * FF))[lane];
        float c0 = coef * w0, c1 = coef * w1;
        acc.x += c0 * m0.x; acc.y += c0 * m0.y; acc.z += c0 * m0.z; acc.w += c0 * m0.w;
        acc.x += c1 * m1.x; acc.y += c1 * m1.y; acc.z += c1 * m1.z; acc.w += c1 * m1.w;
    }
    if (i < cnt) {
        int e0 = __shfl_sync(0xffffffffu, entry, i);
        float w0 = awb[((e0 >> 18) << 2) + wcomp];
        float4 m0 = ((const float4*)(mem + (size_t)(e0 & 0x3FFFF) * FF))[lane];
        float c0 = coef * w0;
        acc.x += c0 * m0.x; acc.y += c0 * m0.y; acc.z += c0 * m0.z; acc.w += c0 * m0.w;
    }
}

// ---------------------------------------------------------------------------
// Gather. TWO warps per quad (b,k), k in [0,1024), half = w&1.
//   half 0 owns rows 2k       (acc a) and 2k+2048   (acc bl):
//       a  = od2*w2*cons(k) + od0*w0*car(4k) + od1*w1*cdr(4k+1, skip k==0)
//       bl = od2*w2*cons(k+1024)
//   half 1 owns rows 2k+1     (acc a) and 2k+2049   (acc bl):
//       a  = od2*w3*cons(k) + od0*w0*car(4k+2) + od1*w1*cdr(4k+3)
//            + (k==0: od2*root)
//       bl = od2*w3*cons(k+1024)
// Paired warps are adjacent in the same block, so the shared cons-row reads
// hit L1/L2 for the second reader. No output row is written by two warps.
// Lane l holds float4 chunk l of each 128-float row.
// ---------------------------------------------------------------------------
__global__ void __launch_bounds__(256) gather_kernel(
    const float* __restrict__ mem,       // (N, F)
    const float* __restrict__ arg_w,     // (B, L, 4)
    const float* __restrict__ root,      // (B, F)
    const float* __restrict__ op_dist,   // (B, 3)
    float* __restrict__ out)             // (B, R, F)
{
    int w = blockIdx.x * (blockDim.x >> 5) + (threadIdx.x >> 5);  // [0, 65536)
    if (w >= BB * 2048) return;
    const int lane = threadIdx.x & 31;
    const int half = w & 1;
    const int q = w >> 1;               // quad index [0, 32768)
    const int b = q >> 10;
    const int k = q & 1023;
    const int base = b * RR;

    const float od0 = op_dist[b * 3 + 0];
    const float od1 = op_dist[b * 3 + 1];
    const float od2 = op_dist[b * 3 + 2];
    const float* awb = arg_w + ((size_t)b << 9);   // b * L * 4

    // bucket ids for this warp
    const int bk_ch  = base + k;                   // heavy cons
    const int bk_cl  = base + k + 1024;            // light cons
    const int bk_car = base + 4 * k + 2 * half;    // car
    const int bk_cdr = bk_car + 1;                 // cdr

    // counts (warp-uniform)
    int cch = min(g_count[bk_ch], CAP);
    int ccl = min(g_count[bk_cl], CAP);
    int2 ccd = *(const int2*)&g_count[bk_car];     // {car, cdr} (8B-aligned)
    int ccar = min(ccd.x, CAP);
    int ccdr = min(ccd.y, CAP);
    if (k == 0 && half == 0) ccdr = 0;             // role 1 never contributes via cdr

    // preload entries (4 independent LDGs)
    int e_ch  = (lane < cch)  ? g_bucket[bk_ch  * CAP + lane] : 0;
    int e_cl  = (lane < ccl)  ? g_bucket[bk_cl  * CAP + lane] : 0;
    int e_car = (lane < ccar) ? g_bucket[bk_car * CAP + lane] : 0;
    int e_cdr = (lane < ccdr) ? g_bucket[bk_cdr * CAP + lane] : 0;

    float4 a  = make_float4(0.f, 0.f, 0.f, 0.f);   // heavy row 2k+half
    float4 bl = make_float4(0.f, 0.f, 0.f, 0.f);   // light row 2k+2048+half

    const int wc_cons = 2 + half;                  // w2 for even rows, w3 for odd
    accum_one(mem, awb, e_ch,  cch,  lane, od2, wc_cons, a);
    accum_one(mem, awb, e_cl,  ccl,  lane, od2, wc_cons, bl);
    accum_one(mem, awb, e_car, ccar, lane, od0, 0, a);
    accum_one(mem, awb, e_cdr, ccdr, lane, od1, 1, a);

    if (k == 0 && half == 1) {                     // row 1 += od2 * root_filler[b]
        float4 rf = ((const float4*)(root + ((size_t)b << 7)))[lane];
        a.x += od2 * rf.x; a.y += od2 * rf.y; a.z += od2 * rf.z; a.w += od2 * rf.w;
    }

    float* oh = out + ((size_t)base + 2 * (size_t)k + half) * FF;
    ((float4*)oh)[lane] = a;                       // row 2k+half
    ((float4*)(oh + (size_t)2048 * FF))[lane] = bl; // row 2k+2048+half
}

// ---------------------------------------------------------------------------
extern "C" void kernel_launch(void* const* d_in, const int* in_sizes, int n_in,
                              void* d_out, int out_size) {
    const float* mem     = (const float*)d_in[0];
    const float* arg_w   = (const float*)d_in[1];
    const float* root    = (const float*)d_in[2];
    const float* op_dist = (const float*)d_in[3];
    const int*   batch_i = (const int*)d_in[4];
    const int*   slot_i  = (const int*)d_in[5];
    const int*   role_i  = (const int*)d_in[6];
    float* out = (float*)d_out;

    void* cnt_ptr = nullptr;
    cudaGetSymbolAddress(&cnt_ptr, g_count);
    cudaMemsetAsync(cnt_ptr, 0, sizeof(int) * BB * RR, 0);

    build_buckets_kernel<<<(NITEMS / 4 + 255) / 256, 256>>>(
        (const int4*)batch_i, (const int4*)slot_i, (const int4*)role_i);

    const int nwarps = BB * 2048;                  // 65536
    gather_kernel<<<nwarps / 8, 256>>>(mem, arg_w, root, op_dist, out);
}

// round 10
// speedup vs baseline: 1.5883x; 1.0992x over previous
#include <cuda_runtime.h>
#include <cstdint>

#define BB 32
#define LL 128
#define FF 128
#define RR 4096
#define NITEMS 262144
#define CAP 32

// Scratch (device globals; no allocation allowed)
__device__ int g_count[BB * RR];           // 512 KB (memset 0 per launch)
__device__ int g_bucket[BB * RR * CAP];    // 16 MB, entry = (slot<<18)|item

// ---------------------------------------------------------------------------
// Bucketize items by (batch, role), 4 items per thread via int4 loads.
// ---------------------------------------------------------------------------
__device__ __forceinline__ void put_item(int b, int s, int r, int item) {
    int bkt = b * RR + r;
    int pos = atomicAdd(&g_count[bkt], 1);
    if (pos < CAP) g_bucket[bkt * CAP + pos] = (s << 18) | item;
}

__global__ void build_buckets_kernel(const int4* __restrict__ batch_idx,
                                     const int4* __restrict__ slot_idx,
                                     const int4* __restrict__ role_idx) {
    int t = blockIdx.x * blockDim.x + threadIdx.x;
    if (t >= NITEMS / 4) return;
    int4 b4 = batch_idx[t];
    int4 s4 = slot_idx[t];
    int4 r4 = role_idx[t];
    int item = t << 2;
    put_item(b4.x, s4.x, r4.x, item + 0);
    put_item(b4.y, s4.y, r4.y, item + 1);
    put_item(b4.z, s4.z, r4.z, item + 2);
    put_item(b4.w, s4.w, r4.w, item + 3);
}

// ---------------------------------------------------------------------------
// cp.async helpers
// ---------------------------------------------------------------------------
__device__ __forceinline__ uint32_t smem_u32(const void* p) {
    uint32_t a;
    asm("{ .reg .u64 t; cvta.to.shared.u64 t, %1; cvt.u32.u64 %0, t; }"
        : "=r"(a) : "l"(p));
    return a;
}
__device__ __forceinline__ void cp_async16(uint32_t dst, const void* src) {
    asm volatile("cp.async.cg.shared.global [%0], [%1], 16;" :: "r"(dst), "l"(src));
}
__device__ __forceinline__ void cp_commit_wait0() {
    asm volatile("cp.async.commit_group;");
    asm volatile("cp.async.wait_group 0;");
}

// ---------------------------------------------------------------------------
// Gather. TWO warps per quad (b,k), k in [0,1024), half = w&1 (as R8):
//   half 0 owns rows 2k (acc a) and 2k+2048 (acc bl)
//   half 1 owns rows 2k+1 (acc a) and 2k+2049 (acc bl), +root at k==0
// Buckets: cons(k)->a [w2/w3], cons(k+1024)->bl [w2/w3],
//          car(4k+2h)->a [w0*od0], cdr(4k+2h+1)->a [w1*od1, skip role 1]
// All 4 buckets compacted into one per-warp smem worklist; rows fetched with
// chunks of 8 cp.async (16B/lane) so 8 row loads are in flight per warp.
// ---------------------------------------------------------------------------
#define WPB 8          // warps per block
#define CHUNK 8        // rows in flight per warp

__global__ void __launch_bounds__(256) gather_kernel(
    const float* __restrict__ mem,       // (N, F)
    const float* __restrict__ arg_w,     // (B, L, 4)
    const float* __restrict__ root,      // (B, F)
    const float* __restrict__ op_dist,   // (B, 3)
    float* __restrict__ out)             // (B, R, F)
{
    __shared__ int    s_pk[WPB][4 * CAP];              // (item<<1)|accbit
    __shared__ float  s_cf[WPB][4 * CAP];              // coefficient
    __shared__ float4 s_rows[WPB][CHUNK][32];          // row staging

    int w = blockIdx.x * (blockDim.x >> 5) + (threadIdx.x >> 5);  // [0, 65536)
    const int lane = threadIdx.x & 31;
    const int wid  = (threadIdx.x >> 5);
    if (w >= BB * 2048) return;
    const int half = w & 1;
    const int q = w >> 1;
    const int b = q >> 10;
    const int k = q & 1023;
    const int base = b * RR;

    const float od0 = op_dist[b * 3 + 0];
    const float od1 = op_dist[b * 3 + 1];
    const float od2 = op_dist[b * 3 + 2];
    const float* awb = arg_w + ((size_t)b << 9);

    const int bk_ch  = base + k;
    const int bk_cl  = base + k + 1024;
    const int bk_car = base + 4 * k + 2 * half;
    const int bk_cdr = bk_car + 1;

    // counts (warp-uniform)
    int cch = min(g_count[bk_ch], CAP);
    int ccl = min(g_count[bk_cl], CAP);
    int2 ccd = *(const int2*)&g_count[bk_car];
    int ccar = min(ccd.x, CAP);
    int ccdr = min(ccd.y, CAP);
    if (k == 0 && half == 0) ccdr = 0;     // role 1 never contributes via cdr

    // preload entries (4 independent LDGs); e=0 defaults are never consumed
    int e_ch  = (lane < cch)  ? g_bucket[bk_ch  * CAP + lane] : 0;
    int e_cl  = (lane < ccl)  ? g_bucket[bk_cl  * CAP + lane] : 0;
    int e_car = (lane < ccar) ? g_bucket[bk_car * CAP + lane] : 0;
    int e_cdr = (lane < ccdr) ? g_bucket[bk_cdr * CAP + lane] : 0;

    // per-lane coefficients (weights folded here, not in the hot loop)
    const int wc = 2 + half;                                 // w2 / w3
    float c_ch  = od2 * awb[(((e_ch  >> 18) & 127) << 2) + wc];
    float c_cl  = od2 * awb[(((e_cl  >> 18) & 127) << 2) + wc];
    float c_car = od0 * awb[(((e_car >> 18) & 127) << 2) + 0];
    float c_cdr = od1 * awb[(((e_cdr >> 18) & 127) << 2) + 1];

    // compact worklist into smem: [ch | cl | car | cdr]
    int p1 = cch, p2 = p1 + ccl, p3 = p2 + ccar;
    int T = p3 + ccdr;
    if (lane < cch)  { s_pk[wid][lane]      = ((e_ch  & 0x3FFFF) << 1) | 0; s_cf[wid][lane]      = c_ch;  }
    if (lane < ccl)  { s_pk[wid][p1 + lane] = ((e_cl  & 0x3FFFF) << 1) | 1; s_cf[wid][p1 + lane] = c_cl;  }
    if (lane < ccar) { s_pk[wid][p2 + lane] = ((e_car & 0x3FFFF) << 1) | 0; s_cf[wid][p2 + lane] = c_car; }
    if (lane < ccdr) { s_pk[wid][p3 + lane] = ((e_cdr & 0x3FFFF) << 1) | 0; s_cf[wid][p3 + lane] = c_cdr; }
    __syncwarp();

    float4 a  = make_float4(0.f, 0.f, 0.f, 0.f);
    float4 bl = make_float4(0.f, 0.f, 0.f, 0.f);

    for (int cs = 0; cs < T; cs += CHUNK) {
        int n = min(T - cs, CHUNK);
        // issue n independent 16B cp.asyncs (this lane's slice of each row)
#pragma unroll
        for (int u = 0; u < CHUNK; u++) {
            if (u < n) {
                int pk = s_pk[wid][cs + u];                  // broadcast LDS
                const float4* src = (const float4*)(mem + (size_t)(pk >> 1) * FF) + lane;
                cp_async16(smem_u32(&s_rows[wid][u][lane]), src);
            }
        }
        cp_commit_wait0();
        // consume: each lane reads only the bytes it fetched (no sync needed)
#pragma unroll
        for (int u = 0; u < CHUNK; u++) {
            if (u < n) {
                float4 m = s_rows[wid][u][lane];
                int pk  = s_pk[wid][cs + u];
                float c = s_cf[wid][cs + u];
                if (pk & 1) {
                    bl.x += c * m.x; bl.y += c * m.y; bl.z += c * m.z; bl.w += c * m.w;
                } else {
                    a.x += c * m.x; a.y += c * m.y; a.z += c * m.z; a.w += c * m.w;
                }
            }
        }
    }

    if (k == 0 && half == 1) {             // row 1 += od2 * root_filler[b]
        float4 rf = ((const float4*)(root + ((size_t)b << 7)))[lane];
        a.x += od2 * rf.x; a.y += od2 * rf.y; a.z += od2 * rf.z; a.w += od2 * rf.w;
    }

    float* oh = out + ((size_t)base + 2 * (size_t)k + half) * FF;
    ((float4*)oh)[lane] = a;                            // row 2k+half
    ((float4*)(oh + (size_t)2048 * FF))[lane] = bl;     // row 2k+2048+half
}

// ---------------------------------------------------------------------------
extern "C" void kernel_launch(void* const* d_in, const int* in_sizes, int n_in,
                              void* d_out, int out_size) {
    const float* mem     = (const float*)d_in[0];
    const float* arg_w   = (const float*)d_in[1];
    const float* root    = (const float*)d_in[2];
    const float* op_dist = (const float*)d_in[3];
    const int*   batch_i = (const int*)d_in[4];
    const int*   slot_i  = (const int*)d_in[5];
    const int*   role_i  = (const int*)d_in[6];
    float* out = (float*)d_out;

    void* cnt_ptr = nullptr;
    cudaGetSymbolAddress(&cnt_ptr, g_count);
    cudaMemsetAsync(cnt_ptr, 0, sizeof(int) * BB * RR, 0);

    build_buckets_kernel<<<(NITEMS / 4 + 255) / 256, 256>>>(
        (const int4*)batch_i, (const int4*)slot_i, (const int4*)role_i);

    const int nwarps = BB * 2048;                  // 65536
    gather_kernel<<<nwarps / 8, 256>>>(mem, arg_w, root, op_dist, out);
}

// round 11
// speedup vs baseline: 1.7017x; 1.0714x over previous
#include <cuda_runtime.h>
#include <cstdint>

#define BB 32
#define LL 128
#define FF 128
#define RR 4096
#define NITEMS 262144
#define CAP 32

// Scratch (device globals; no allocation allowed)
__device__ int g_count[BB * RR];           // 512 KB (memset 0 per launch)
__device__ int g_bucket[BB * RR * CAP];    // 16 MB, entry = (slot<<18)|item

// ---------------------------------------------------------------------------
// Bucketize items by (batch, role), 4 items per thread via int4 loads.
// ---------------------------------------------------------------------------
__device__ __forceinline__ void put_item(int b, int s, int r, int item) {
    int bkt = b * RR + r;
    int pos = atomicAdd(&g_count[bkt], 1);
    if (pos < CAP) g_bucket[bkt * CAP + pos] = (s << 18) | item;
}

__global__ void build_buckets_kernel(const int4* __restrict__ batch_idx,
                                     const int4* __restrict__ slot_idx,
                                     const int4* __restrict__ role_idx) {
    int t = blockIdx.x * blockDim.x + threadIdx.x;
    if (t >= NITEMS / 4) return;
    int4 b4 = batch_idx[t];
    int4 s4 = slot_idx[t];
    int4 r4 = role_idx[t];
    int item = t << 2;
    put_item(b4.x, s4.x, r4.x, item + 0);
    put_item(b4.y, s4.y, r4.y, item + 1);
    put_item(b4.z, s4.z, r4.z, item + 2);
    put_item(b4.w, s4.w, r4.w, item + 3);
}

// ---------------------------------------------------------------------------
// cp.async helpers
// ---------------------------------------------------------------------------
__device__ __forceinline__ uint32_t smem_u32(const void* p) {
    uint32_t a;
    asm("{ .reg .u64 t; cvta.to.shared.u64 t, %1; cvt.u32.u64 %0, t; }"
        : "=r"(a) : "l"(p));
    return a;
}
__device__ __forceinline__ void cp_async16(uint32_t dst, const void* src) {
    asm volatile("cp.async.cg.shared.global [%0], [%1], 16;" :: "r"(dst), "l"(src));
}
__device__ __forceinline__ void cp_commit_wait0() {
    asm volatile("cp.async.commit_group;");
    asm volatile("cp.async.wait_group 0;");
}

// ---------------------------------------------------------------------------
// Gather. TWO warps per quad (b,k), k in [0,1024), half = w&1:
//   half 0 owns rows 2k (acc a) and 2k+2048 (acc bl)
//   half 1 owns rows 2k+1 (acc a) and 2k+2049 (acc bl), +root at k==0
// Buckets: cons(k)->a [w2/w3], cons(k+1024)->bl [w2/w3],
//          car(4k+2h)->a [w0*od0], cdr(4k+2h+1)->a [w1*od1, skip role 1]
// Every block's 8 warps share one batch b: arg_w[b] (2KB) staged in smem.
// Entry LDGs are unconditional (parallel with count LDGs). Rows fetched in
// chunks of 8 via cp.async (16B/lane), consumed with no syncs in the loop.
// ---------------------------------------------------------------------------
#define WPB 8          // warps per block
#define CHUNK 8        // rows in flight per warp

__global__ void __launch_bounds__(256) gather_kernel(
    const float* __restrict__ mem,       // (N, F)
    const float* __restrict__ arg_w,     // (B, L, 4)
    const float* __restrict__ root,      // (B, F)
    const float* __restrict__ op_dist,   // (B, 3)
    float* __restrict__ out)             // (B, R, F)
{
    __shared__ float  s_awb[LL * 4];                   // 2KB: arg_w[b]
    __shared__ int2   s_wl[WPB][4 * CAP];              // {pk=(item<<1)|bit, cf bits}
    __shared__ float4 s_rows[WPB][CHUNK][32];          // row staging

    int w = blockIdx.x * WPB + (threadIdx.x >> 5);     // [0, 65536)
    const int lane = threadIdx.x & 31;
    const int wid  = (threadIdx.x >> 5);
    const int half = w & 1;
    const int q = w >> 1;
    const int b = q >> 10;
    const int k = q & 1023;
    const int base = b * RR;

    // cooperative stage of arg_w[b] (batch uniform across the block)
    {
        const float* awg = arg_w + ((size_t)b << 9);
        s_awb[threadIdx.x]       = awg[threadIdx.x];
        s_awb[threadIdx.x + 256] = awg[threadIdx.x + 256];
    }

    const float od0 = op_dist[b * 3 + 0];
    const float od1 = op_dist[b * 3 + 1];
    const float od2 = op_dist[b * 3 + 2];

    const int bk_ch  = base + k;
    const int bk_cl  = base + k + 1024;
    const int bk_car = base + 4 * k + 2 * half;
    const int bk_cdr = bk_car + 1;

    // counts and entries issued together (entries unconditional: the array is
    // always-valid memory and garbage lanes are never consumed)
    int cch_r = g_count[bk_ch];
    int ccl_r = g_count[bk_cl];
    int2 ccd  = *(const int2*)&g_count[bk_car];
    int e_ch  = g_bucket[bk_ch  * CAP + lane];
    int e_cl  = g_bucket[bk_cl  * CAP + lane];
    int e_car = g_bucket[bk_car * CAP + lane];
    int e_cdr = g_bucket[bk_cdr * CAP + lane];

    int cch  = min(cch_r, CAP);
    int ccl  = min(ccl_r, CAP);
    int ccar = min(ccd.x, CAP);
    int ccdr = min(ccd.y, CAP);
    if (k == 0 && half == 0) ccdr = 0;     // role 1 never contributes via cdr

    __syncthreads();                        // s_awb ready

    // per-lane coefficients from smem (29cyc, no L1 traffic)
    const int wc = 2 + half;                               // w2 / w3
    float c_ch  = od2 * s_awb[(((e_ch  >> 18) & 127) << 2) + wc];
    float c_cl  = od2 * s_awb[(((e_cl  >> 18) & 127) << 2) + wc];
    float c_car = od0 * s_awb[(((e_car >> 18) & 127) << 2) + 0];
    float c_cdr = od1 * s_awb[(((e_cdr >> 18) & 127) << 2) + 1];

    // compact worklist: [ch | cl | car | cdr]
    int p1 = cch, p2 = p1 + ccl, p3 = p2 + ccar;
    int T = p3 + ccdr;
    if (lane < cch)  s_wl[wid][lane]      = make_int2(((e_ch  & 0x3FFFF) << 1) | 0, __float_as_int(c_ch));
    if (lane < ccl)  s_wl[wid][p1 + lane] = make_int2(((e_cl  & 0x3FFFF) << 1) | 1, __float_as_int(c_cl));
    if (lane < ccar) s_wl[wid][p2 + lane] = make_int2(((e_car & 0x3FFFF) << 1) | 0, __float_as_int(c_car));
    if (lane < ccdr) s_wl[wid][p3 + lane] = make_int2(((e_cdr & 0x3FFFF) << 1) | 0, __float_as_int(c_cdr));
    __syncwarp();

    float4 a  = make_float4(0.f, 0.f, 0.f, 0.f);
    float4 bl = make_float4(0.f, 0.f, 0.f, 0.f);

    for (int cs = 0; cs < T; cs += CHUNK) {
        int n = min(T - cs, CHUNK);
        // issue n independent 16B cp.asyncs (this lane's slice of each row)
#pragma unroll
        for (int u = 0; u < CHUNK; u++) {
            if (u < n) {
                int pk = s_wl[wid][cs + u].x;              // broadcast LDS
                const float4* src = (const float4*)(mem + (size_t)(pk >> 1) * FF) + lane;
                cp_async16(smem_u32(&s_rows[wid][u][lane]), src);
            }
        }
        cp_commit_wait0();
        // consume: each lane reads only the bytes it fetched (no sync needed)
#pragma unroll
        for (int u = 0; u < CHUNK; u++) {
            if (u < n) {
                float4 m = s_rows[wid][u][lane];
                int2 wl = s_wl[wid][cs + u];               // one LDS.64
                float c = __int_as_float(wl.y);
                if (wl.x & 1) {
                    bl.x += c * m.x; bl.y += c * m.y; bl.z += c * m.z; bl.w += c * m.w;
                } else {
                    a.x += c * m.x; a.y += c * m.y; a.z += c * m.z; a.w += c * m.w;
                }
            }
        }
    }

    if (k == 0 && half == 1) {             // row 1 += od2 * root_filler[b]
        float4 rf = ((const float4*)(root + ((size_t)b << 7)))[lane];
        a.x += od2 * rf.x; a.y += od2 * rf.y; a.z += od2 * rf.z; a.w += od2 * rf.w;
    }

    float* oh = out + ((size_t)base + 2 * (size_t)k + half) * FF;
    ((float4*)oh)[lane] = a;                            // row 2k+half
    ((float4*)(oh + (size_t)2048 * FF))[lane] = bl;     // row 2k+2048+half
}

// ---------------------------------------------------------------------------
extern "C" void kernel_launch(void* const* d_in, const int* in_sizes, int n_in,
                              void* d_out, int out_size) {
    const float* mem     = (const float*)d_in[0];
    const float* arg_w   = (const float*)d_in[1];
    const float* root    = (const float*)d_in[2];
    const float* op_dist = (const float*)d_in[3];
    const int*   batch_i = (const int*)d_in[4];
    const int*   slot_i  = (const int*)d_in[5];
    const int*   role_i  = (const int*)d_in[6];
    float* out = (float*)d_out;

    void* cnt_ptr = nullptr;
    cudaGetSymbolAddress(&cnt_ptr, g_count);
    cudaMemsetAsync(cnt_ptr, 0, sizeof(int) * BB * RR, 0);

    build_buckets_kernel<<<(NITEMS / 4 + 255) / 256, 256>>>(
        (const int4*)batch_i, (const int4*)slot_i, (const int4*)role_i);

    const int nwarps = BB * 2048;                  // 65536
    gather_kernel<<<nwarps / WPB, 256>>>(mem, arg_w, root, op_dist, out);
}

// round 12
// speedup vs baseline: 1.9028x; 1.1182x over previous
#include <cuda_runtime.h>
#include <cstdint>

#define BB 32
#define LL 128
#define FF 128
#define RR 4096
#define NITEMS 262144
#define CAP 32

// Scratch (device globals; no allocation allowed)
__device__ int g_count[BB * RR];           // 512 KB (memset 0 per launch)
__device__ int g_bucket[BB * RR * CAP];    // 16 MB, entry = (slot<<18)|item

// ---------------------------------------------------------------------------
// Bucketize items by (batch, role), 4 items per thread via int4 loads.
// ---------------------------------------------------------------------------
__device__ __forceinline__ void put_item(int b, int s, int r, int item) {
    int bkt = b * RR + r;
    int pos = atomicAdd(&g_count[bkt], 1);
    if (pos < CAP) g_bucket[bkt * CAP + pos] = (s << 18) | item;
}

__global__ void build_buckets_kernel(const int4* __restrict__ batch_idx,
                                     const int4* __restrict__ slot_idx,
                                     const int4* __restrict__ role_idx) {
    int t = blockIdx.x * blockDim.x + threadIdx.x;
    if (t >= NITEMS / 4) return;
    int4 b4 = batch_idx[t];
    int4 s4 = slot_idx[t];
    int4 r4 = role_idx[t];
    int item = t << 2;
    put_item(b4.x, s4.x, r4.x, item + 0);
    put_item(b4.y, s4.y, r4.y, item + 1);
    put_item(b4.z, s4.z, r4.z, item + 2);
    put_item(b4.w, s4.w, r4.w, item + 3);
}

// ---------------------------------------------------------------------------
// cp.async helpers
// ---------------------------------------------------------------------------
__device__ __forceinline__ uint32_t smem_u32(const void* p) {
    uint32_t a;
    asm("{ .reg .u64 t; cvta.to.shared.u64 t, %1; cvt.u32.u64 %0, t; }"
        : "=r"(a) : "l"(p));
    return a;
}
__device__ __forceinline__ void cp_async16(uint32_t dst, const void* src) {
    asm volatile("cp.async.cg.shared.global [%0], [%1], 16;" :: "r"(dst), "l"(src));
}
__device__ __forceinline__ void cp_commit_wait0() {
    asm volatile("cp.async.commit_group;");
    asm volatile("cp.async.wait_group 0;");
}

// ---------------------------------------------------------------------------
// Gather. ONE warp per quad (b,k), k in [0,1024). Owns 4 rows / 4 accums:
//   a0 = row 2k      <- cons(k)[w2*od2] + car(4k)[w0*od0] + cdr(4k+1)[w1*od1, skip role 1]
//   a1 = row 2k+1    <- cons(k)[w3*od2] + car(4k+2) + cdr(4k+3) + (k==0: od2*root)
//   b0 = row 2k+2048 <- cons(k+1024)[w2*od2]
//   b1 = row 2k+2049 <- cons(k+1024)[w3*od2]
// One unified worklist (T<=192, avg ~12); cons items carry two coefficients
// and feed two accumulators off a single row fetch. Rows fetched in chunks of
// 6 via cp.async (16B/lane), consumed with no syncs inside the loop.
// Codes in wl.x low bits: 0=cons->a pair, 1=cons->b pair, 2=single->a0, 3=single->a1.
// ---------------------------------------------------------------------------
#define WPB 8          // warps per block
#define CHUNK 6        // rows in flight per warp
#define WLMAX (6 * CAP)

__global__ void __launch_bounds__(256) gather_kernel(
    const float* __restrict__ mem,       // (N, F)
    const float* __restrict__ arg_w,     // (B, L, 4)
    const float* __restrict__ root,      // (B, F)
    const float* __restrict__ op_dist,   // (B, 3)
    float* __restrict__ out)             // (B, R, F)
{
    __shared__ float  s_awb[LL * 4];                   // 2KB: arg_w[b]
    __shared__ int2   s_wl[WPB][WLMAX];                // 12KB: {pk, coeff0}
    __shared__ float  s_cO[WPB][2 * CAP];              // 2KB: cons odd-row coeff
    __shared__ float4 s_rows[WPB][CHUNK][32];          // 24KB: row staging

    int q = blockIdx.x * WPB + (threadIdx.x >> 5);     // quad [0, 32768)
    const int lane = threadIdx.x & 31;
    const int wid  = (threadIdx.x >> 5);
    const int b = q >> 10;
    const int k = q & 1023;
    const int base = b * RR;

    // cooperative stage of arg_w[b] (batch uniform across the block)
    {
        const float* awg = arg_w + ((size_t)b << 9);
        s_awb[threadIdx.x]       = awg[threadIdx.x];
        s_awb[threadIdx.x + 256] = awg[threadIdx.x + 256];
    }

    const float od0 = op_dist[b * 3 + 0];
    const float od1 = op_dist[b * 3 + 1];
    const float od2 = op_dist[b * 3 + 2];

    const int bk_ch = base + k;            // cons heavy (rows 2k, 2k+1)
    const int bk_cl = base + k + 1024;     // cons light (rows 2k+2048, 2k+2049)
    const int bk_c  = base + 4 * k;        // car0, cdr0, car1, cdr1

    // counts + entries, all issued together (entries unconditional; the array
    // is always-valid memory and garbage lanes are never consumed)
    int  cch_r = g_count[bk_ch];
    int  ccl_r = g_count[bk_cl];
    int4 cc4   = *(const int4*)&g_count[bk_c];
    int e_ch = g_bucket[bk_ch * CAP + lane];
    int e_cl = g_bucket[bk_cl * CAP + lane];
    int e_r0 = g_bucket[(bk_c + 0) * CAP + lane];
    int e_r1 = g_bucket[(bk_c + 1) * CAP + lane];
    int e_r2 = g_bucket[(bk_c + 2) * CAP + lane];
    int e_r3 = g_bucket[(bk_c + 3) * CAP + lane];

    int cch = min(cch_r, CAP);
    int ccl = min(ccl_r, CAP);
    int c0  = min(cc4.x, CAP);
    int c1  = min(cc4.y, CAP);
    int c2  = min(cc4.z, CAP);
    int c3  = min(cc4.w, CAP);
    if (k == 0) c1 = 0;                    // role 1 never contributes via cdr

    __syncthreads();                       // s_awb ready

    // per-lane coefficients from smem
    float2 wch = *(const float2*)&s_awb[(((e_ch >> 18) & 127) << 2) + 2]; // w2,w3
    float2 wcl = *(const float2*)&s_awb[(((e_cl >> 18) & 127) << 2) + 2];
    float cw0 = od0 * s_awb[(((e_r0 >> 18) & 127) << 2) + 0];
    float cw1 = od1 * s_awb[(((e_r1 >> 18) & 127) << 2) + 1];
    float cw2 = od0 * s_awb[(((e_r2 >> 18) & 127) << 2) + 0];
    float cw3 = od1 * s_awb[(((e_r3 >> 18) & 127) << 2) + 1];

    // build worklist: [cons_h | cons_l | car0 | cdr0 | car1 | cdr1]
    int p1 = cch, p2 = p1 + ccl, p3 = p2 + c0, p4 = p3 + c1, p5 = p4 + c2;
    int T = p5 + c3;
    if (lane < cch) {
        s_wl[wid][lane] = make_int2(((e_ch & 0x3FFFF) << 2) | 0,
                                    __float_as_int(od2 * wch.x));
        s_cO[wid][lane] = od2 * wch.y;
    }
    if (lane < ccl) {
        s_wl[wid][p1 + lane] = make_int2(((e_cl & 0x3FFFF) << 2) | 1,
                                         __float_as_int(od2 * wcl.x));
        s_cO[wid][p1 + lane] = od2 * wcl.y;
    }
    if (lane < c0) s_wl[wid][p2 + lane] = make_int2(((e_r0 & 0x3FFFF) << 2) | 2, __float_as_int(cw0));
    if (lane < c1) s_wl[wid][p3 + lane] = make_int2(((e_r1 & 0x3FFFF) << 2) | 2, __float_as_int(cw1));
    if (lane < c2) s_wl[wid][p4 + lane] = make_int2(((e_r2 & 0x3FFFF) << 2) | 3, __float_as_int(cw2));
    if (lane < c3) s_wl[wid][p5 + lane] = make_int2(((e_r3 & 0x3FFFF) << 2) | 3, __float_as_int(cw3));
    __syncwarp();

    float4 a0 = make_float4(0.f, 0.f, 0.f, 0.f);
    float4 a1 = make_float4(0.f, 0.f, 0.f, 0.f);
    float4 b0 = make_float4(0.f, 0.f, 0.f, 0.f);
    float4 b1 = make_float4(0.f, 0.f, 0.f, 0.f);

    for (int cs = 0; cs < T; cs += CHUNK) {
        int n = min(T - cs, CHUNK);
        // issue n independent 16B cp.asyncs (this lane's slice of each row)
#pragma unroll
        for (int u = 0; u < CHUNK; u++) {
            if (u < n) {
                int pk = s_wl[wid][cs + u].x;              // broadcast LDS
                const float4* src = (const float4*)(mem + (size_t)(pk >> 2) * FF) + lane;
                cp_async16(smem_u32(&s_rows[wid][u][lane]), src);
            }
        }
        cp_commit_wait0();
        // consume: each lane reads only the bytes it fetched (no sync needed)
#pragma unroll
        for (int u = 0; u < CHUNK; u++) {
            if (u < n) {
                float4 m = s_rows[wid][u][lane];
                int2 wl = s_wl[wid][cs + u];               // one LDS.64
                float c = __int_as_float(wl.y);
                int code = wl.x & 3;
                if (code < 2) {
                    float cO = s_cO[wid][cs + u];
                    if (code == 0) {
                        a0.x += c * m.x; a0.y += c * m.y; a0.z += c * m.z; a0.w += c * m.w;
                        a1.x += cO * m.x; a1.y += cO * m.y; a1.z += cO * m.z; a1.w += cO * m.w;
                    } else {
                        b0.x += c * m.x; b0.y += c * m.y; b0.z += c * m.z; b0.w += c * m.w;
                        b1.x += cO * m.x; b1.y += cO * m.y; b1.z += cO * m.z; b1.w += cO * m.w;
                    }
                } else if (code == 2) {
                    a0.x += c * m.x; a0.y += c * m.y; a0.z += c * m.z; a0.w += c * m.w;
                } else {
                    a1.x += c * m.x; a1.y += c * m.y; a1.z += c * m.z; a1.w += c * m.w;
                }
            }
        }
    }

    if (k == 0) {                          // row 1 += od2 * root_filler[b]
        float4 rf = ((const float4*)(root + ((size_t)b << 7)))[lane];
        a1.x += od2 * rf.x; a1.y += od2 * rf.y; a1.z += od2 * rf.z; a1.w += od2 * rf.w;
    }

    float* oh = out + ((size_t)base + 2 * (size_t)k) * FF;
    ((float4*)oh)[lane]        = a0;                    // row 2k
    ((float4*)(oh + FF))[lane] = a1;                    // row 2k+1
    float* ol = oh + (size_t)2048 * FF;
    ((float4*)ol)[lane]        = b0;                    // row 2k+2048
    ((float4*)(ol + FF))[lane] = b1;                    // row 2k+2049
}

// ---------------------------------------------------------------------------
extern "C" void kernel_launch(void* const* d_in, const int* in_sizes, int n_in,
                              void* d_out, int out_size) {
    const float* mem     = (const float*)d_in[0];
    const float* arg_w   = (const float*)d_in[1];
    const float* root    = (const float*)d_in[2];
    const float* op_dist = (const float*)d_in[3];
    const int*   batch_i = (const int*)d_in[4];
    const int*   slot_i  = (const int*)d_in[5];
    const int*   role_i  = (const int*)d_in[6];
    float* out = (float*)d_out;

    void* cnt_ptr = nullptr;
    cudaGetSymbolAddress(&cnt_ptr, g_count);
    cudaMemsetAsync(cnt_ptr, 0, sizeof(int) * BB * RR, 0);

    build_buckets_kernel<<<(NITEMS / 4 + 255) / 256, 256>>>(
        (const int4*)batch_i, (const int4*)slot_i, (const int4*)role_i);

    const int nquads = BB * 1024;                  // 32768
    gather_kernel<<<nquads / WPB, 256>>>(mem, arg_w, root, op_dist, out);
}

// round 13
// speedup vs baseline: 1.9724x; 1.0366x over previous
#include <cuda_runtime.h>
#include <cstdint>

#define BB 32
#define LL 128
#define FF 128
#define RR 4096
#define NITEMS 262144
#define CAP 32

// Scratch (device globals; no allocation allowed)
__device__ int g_count[BB * RR];           // 512 KB (memset 0 per launch)
__device__ int g_bucket[BB * RR * CAP];    // 16 MB, entry = (slot<<18)|item

// ---------------------------------------------------------------------------
// Bucketize items by (batch, role), 4 items per thread via int4 loads.
// ---------------------------------------------------------------------------
__device__ __forceinline__ void put_item(int b, int s, int r, int item) {
    int bkt = b * RR + r;
    int pos = atomicAdd(&g_count[bkt], 1);
    if (pos < CAP) g_bucket[bkt * CAP + pos] = (s << 18) | item;
}

__global__ void build_buckets_kernel(const int4* __restrict__ batch_idx,
                                     const int4* __restrict__ slot_idx,
                                     const int4* __restrict__ role_idx) {
    int t = blockIdx.x * blockDim.x + threadIdx.x;
    if (t >= NITEMS / 4) return;
    int4 b4 = batch_idx[t];
    int4 s4 = slot_idx[t];
    int4 r4 = role_idx[t];
    int item = t << 2;
    put_item(b4.x, s4.x, r4.x, item + 0);
    put_item(b4.y, s4.y, r4.y, item + 1);
    put_item(b4.z, s4.z, r4.z, item + 2);
    put_item(b4.w, s4.w, r4.w, item + 3);
}

// ---------------------------------------------------------------------------
// cp.async helpers
// ---------------------------------------------------------------------------
__device__ __forceinline__ uint32_t smem_u32(const void* p) {
    uint32_t a;
    asm("{ .reg .u64 t; cvta.to.shared.u64 t, %1; cvt.u32.u64 %0, t; }"
        : "=r"(a) : "l"(p));
    return a;
}
__device__ __forceinline__ void cp_async16(uint32_t dst, const void* src) {
    asm volatile("cp.async.cg.shared.global [%0], [%1], 16;" :: "r"(dst), "l"(src));
}
__device__ __forceinline__ void cp_commit() {
    asm volatile("cp.async.commit_group;");
}
__device__ __forceinline__ void cp_wait1() {
    asm volatile("cp.async.wait_group 1;");
}
__device__ __forceinline__ void cp_wait0() {
    asm volatile("cp.async.wait_group 0;");
}

// ---------------------------------------------------------------------------
// Gather. ONE warp per quad (b,k), k in [0,1024). Owns 4 rows / 4 accums:
//   a0 = row 2k      <- cons(k)[w2*od2] + car(4k)[w0*od0] + cdr(4k+1)[w1*od1, skip role 1]
//   a1 = row 2k+1    <- cons(k)[w3*od2] + car(4k+2) + cdr(4k+3) + (k==0: od2*root)
//   b0 = row 2k+2048 <- cons(k+1024)[w2*od2]
//   b1 = row 2k+2049 <- cons(k+1024)[w3*od2]
// Unified worklist; every item carries (c0, c1) feeding an accumulator PAIR
// (bit 0 of pk selects pair a vs pair b): cons = both nonzero; car/cdr one 0.
// Rows fetched by double-buffered cp.async chunks of 3 (wait_group 1 keeps
// one chunk always in flight).
// ---------------------------------------------------------------------------
#define WPB 8          // warps per block
#define CHUNK 3        // rows per pipeline stage
#define WLMAX (6 * CAP)

__global__ void __launch_bounds__(256) gather_kernel(
    const float* __restrict__ mem,       // (N, F)
    const float* __restrict__ arg_w,     // (B, L, 4)
    const float* __restrict__ root,      // (B, F)
    const float* __restrict__ op_dist,   // (B, 3)
    float* __restrict__ out)             // (B, R, F)
{
    __shared__ float  s_awb[LL * 4];                   // 2KB: arg_w[b]
    __shared__ int2   s_wl[WPB][WLMAX];                // 12KB: {pk=(item<<1)|pairbit, c0}
    __shared__ float  s_c1[WPB][WLMAX];                // 6KB: second coefficient
    __shared__ float4 s_rows[WPB][2][CHUNK][32];       // 24KB: double-buffered staging

    int q = blockIdx.x * WPB + (threadIdx.x >> 5);     // quad [0, 32768)
    const int lane = threadIdx.x & 31;
    const int wid  = (threadIdx.x >> 5);
    const int b = q >> 10;
    const int k = q & 1023;
    const int base = b * RR;

    // cooperative stage of arg_w[b] (batch uniform across the block)
    {
        const float* awg = arg_w + ((size_t)b << 9);
        s_awb[threadIdx.x]       = awg[threadIdx.x];
        s_awb[threadIdx.x + 256] = awg[threadIdx.x + 256];
    }

    const float od0 = op_dist[b * 3 + 0];
    const float od1 = op_dist[b * 3 + 1];
    const float od2 = op_dist[b * 3 + 2];

    const int bk_ch = base + k;            // cons heavy (rows 2k, 2k+1)
    const int bk_cl = base + k + 1024;     // cons light (rows 2k+2048, 2k+2049)
    const int bk_c  = base + 4 * k;        // car0, cdr0, car1, cdr1

    // counts + entries, all issued together (entries unconditional; the array
    // is always-valid memory and garbage lanes are never consumed)
    int  cch_r = g_count[bk_ch];
    int  ccl_r = g_count[bk_cl];
    int4 cc4   = *(const int4*)&g_count[bk_c];
    int e_ch = g_bucket[bk_ch * CAP + lane];
    int e_cl = g_bucket[bk_cl * CAP + lane];
    int e_r0 = g_bucket[(bk_c + 0) * CAP + lane];
    int e_r1 = g_bucket[(bk_c + 1) * CAP + lane];
    int e_r2 = g_bucket[(bk_c + 2) * CAP + lane];
    int e_r3 = g_bucket[(bk_c + 3) * CAP + lane];

    int cch = min(cch_r, CAP);
    int ccl = min(ccl_r, CAP);
    int c0n = min(cc4.x, CAP);
    int c1n = min(cc4.y, CAP);
    int c2n = min(cc4.z, CAP);
    int c3n = min(cc4.w, CAP);
    if (k == 0) c1n = 0;                   // role 1 never contributes via cdr

    __syncthreads();                       // s_awb ready

    // per-lane coefficients from smem
    float2 wch = *(const float2*)&s_awb[(((e_ch >> 18) & 127) << 2) + 2]; // w2,w3
    float2 wcl = *(const float2*)&s_awb[(((e_cl >> 18) & 127) << 2) + 2];
    float cw0 = od0 * s_awb[(((e_r0 >> 18) & 127) << 2) + 0];
    float cw1 = od1 * s_awb[(((e_r1 >> 18) & 127) << 2) + 1];
    float cw2 = od0 * s_awb[(((e_r2 >> 18) & 127) << 2) + 0];
    float cw3 = od1 * s_awb[(((e_r3 >> 18) & 127) << 2) + 1];

    // build worklist: [cons_h | cons_l | car0 | cdr0 | car1 | cdr1]
    int p1 = cch, p2 = p1 + ccl, p3 = p2 + c0n, p4 = p3 + c1n, p5 = p4 + c2n;
    int T = p5 + c3n;
    if (lane < cch) {
        s_wl[wid][lane] = make_int2(((e_ch & 0x3FFFF) << 1) | 0, __float_as_int(od2 * wch.x));
        s_c1[wid][lane] = od2 * wch.y;
    }
    if (lane < ccl) {
        s_wl[wid][p1 + lane] = make_int2(((e_cl & 0x3FFFF) << 1) | 1, __float_as_int(od2 * wcl.x));
        s_c1[wid][p1 + lane] = od2 * wcl.y;
    }
    if (lane < c0n) { s_wl[wid][p2 + lane] = make_int2(((e_r0 & 0x3FFFF) << 1), __float_as_int(cw0)); s_c1[wid][p2 + lane] = 0.f; }
    if (lane < c1n) { s_wl[wid][p3 + lane] = make_int2(((e_r1 & 0x3FFFF) << 1), __float_as_int(cw1)); s_c1[wid][p3 + lane] = 0.f; }
    if (lane < c2n) { s_wl[wid][p4 + lane] = make_int2(((e_r2 & 0x3FFFF) << 1), 0); s_c1[wid][p4 + lane] = cw2; }
    if (lane < c3n) { s_wl[wid][p5 + lane] = make_int2(((e_r3 & 0x3FFFF) << 1), 0); s_c1[wid][p5 + lane] = cw3; }
    __syncwarp();

    float4 a0 = make_float4(0.f, 0.f, 0.f, 0.f);
    float4 a1 = make_float4(0.f, 0.f, 0.f, 0.f);
    float4 b0 = make_float4(0.f, 0.f, 0.f, 0.f);
    float4 b1 = make_float4(0.f, 0.f, 0.f, 0.f);

    const int nc = (T + CHUNK - 1) / CHUNK;            // number of chunks

    // issue chunk 0
    if (nc > 0) {
#pragma unroll
        for (int u = 0; u < CHUNK; u++) {
            if (u < T) {
                int pk = s_wl[wid][u].x;
                const float4* src = (const float4*)(mem + (size_t)(pk >> 1) * FF) + lane;
                cp_async16(smem_u32(&s_rows[wid][0][u][lane]), src);
            }
        }
        cp_commit();
    }

    for (int c = 0; c < nc; c++) {
        int cs = c * CHUNK;
        int n = min(T - cs, CHUNK);
        bool has_next = (c + 1 < nc);
        if (has_next) {
            int cs2 = cs + CHUNK;
            int n2 = min(T - cs2, CHUNK);
#pragma unroll
            for (int u = 0; u < CHUNK; u++) {
                if (u < n2) {
                    int pk = s_wl[wid][cs2 + u].x;
                    const float4* src = (const float4*)(mem + (size_t)(pk >> 1) * FF) + lane;
                    cp_async16(smem_u32(&s_rows[wid][(c + 1) & 1][u][lane]), src);
                }
            }
            cp_commit();
            cp_wait1();                                // previous chunk ready
        } else {
            cp_wait0();
        }
#pragma unroll
        for (int u = 0; u < CHUNK; u++) {
            if (u < n) {
                float4 m = s_rows[wid][c & 1][u][lane];
                int2 wl = s_wl[wid][cs + u];           // one LDS.64
                float cE = __int_as_float(wl.y);
                float cO = s_c1[wid][cs + u];
                if (wl.x & 1) {
                    b0.x += cE * m.x; b0.y += cE * m.y; b0.z += cE * m.z; b0.w += cE * m.w;
                    b1.x += cO * m.x; b1.y += cO * m.y; b1.z += cO * m.z; b1.w += cO * m.w;
                } else {
                    a0.x += cE * m.x; a0.y += cE * m.y; a0.z += cE * m.z; a0.w += cE * m.w;
                    a1.x += cO * m.x; a1.y += cO * m.y; a1.z += cO * m.z; a1.w += cO * m.w;
                }
            }
        }
    }

    if (k == 0) {                          // row 1 += od2 * root_filler[b]
        float4 rf = ((const float4*)(root + ((size_t)b << 7)))[lane];
        a1.x += od2 * rf.x; a1.y += od2 * rf.y; a1.z += od2 * rf.z; a1.w += od2 * rf.w;
    }

    float* oh = out + ((size_t)base + 2 * (size_t)k) * FF;
    ((float4*)oh)[lane]        = a0;                    // row 2k
    ((float4*)(oh + FF))[lane] = a1;                    // row 2k+1
    float* ol = oh + (size_t)2048 * FF;
    ((float4*)ol)[lane]        = b0;                    // row 2k+2048
    ((float4*)(ol + FF))[lane] = b1;                    // row 2k+2049
}

// ---------------------------------------------------------------------------
extern "C" void kernel_launch(void* const* d_in, const int* in_sizes, int n_in,
                              void* d_out, int out_size) {
    const float* mem     = (const float*)d_in[0];
    const float* arg_w   = (const float*)d_in[1];
    const float* root    = (const float*)d_in[2];
    const float* op_dist = (const float*)d_in[3];
    const int*   batch_i = (const int*)d_in[4];
    const int*   slot_i  = (const int*)d_in[5];
    const int*   role_i  = (const int*)d_in[6];
    float* out = (float*)d_out;

    void* cnt_ptr = nullptr;
    cudaGetSymbolAddress(&cnt_ptr, g_count);
    cudaMemsetAsync(cnt_ptr, 0, sizeof(int) * BB * RR, 0);

    build_buckets_kernel<<<(NITEMS / 4 + 255) / 256, 256>>>(
        (const int4*)batch_i, (const int4*)slot_i, (const int4*)role_i);

    const int nquads = BB * 1024;                  // 32768
    gather_kernel<<<nquads / WPB, 256>>>(mem, arg_w, root, op_dist, out);
}

// round 14
// speedup vs baseline: 2.0665x; 1.0477x over previous
#include <cuda_runtime.h>
#include <cstdint>

#define BB 32
#define LL 128
#define FF 128
#define RR 4096
#define NITEMS 262144
#define CAP 32

// Scratch (device globals; no allocation allowed)
__device__ int g_count[BB * RR];           // 512 KB (memset 0 per launch)
__device__ int g_bucket[BB * RR * CAP];    // 16 MB, entry = (slot<<18)|item

// ---------------------------------------------------------------------------
// Bucketize items by (batch, role), 4 items per thread via int4 loads.
// ---------------------------------------------------------------------------
__device__ __forceinline__ void put_item(int b, int s, int r, int item) {
    int bkt = b * RR + r;
    int pos = atomicAdd(&g_count[bkt], 1);
    if (pos < CAP) g_bucket[bkt * CAP + pos] = (s << 18) | item;
}

__global__ void build_buckets_kernel(const int4* __restrict__ batch_idx,
                                     const int4* __restrict__ slot_idx,
                                     const int4* __restrict__ role_idx) {
    int t = blockIdx.x * blockDim.x + threadIdx.x;
    if (t >= NITEMS / 4) return;
    int4 b4 = batch_idx[t];
    int4 s4 = slot_idx[t];
    int4 r4 = role_idx[t];
    int item = t << 2;
    put_item(b4.x, s4.x, r4.x, item + 0);
    put_item(b4.y, s4.y, r4.y, item + 1);
    put_item(b4.z, s4.z, r4.z, item + 2);
    put_item(b4.w, s4.w, r4.w, item + 3);
}

// ---------------------------------------------------------------------------
// cp.async helpers
// ---------------------------------------------------------------------------
__device__ __forceinline__ uint32_t smem_u32(const void* p) {
    uint32_t a;
    asm("{ .reg .u64 t; cvta.to.shared.u64 t, %1; cvt.u32.u64 %0, t; }"
        : "=r"(a) : "l"(p));
    return a;
}
__device__ __forceinline__ void cp_async16(uint32_t dst, const void* src) {
    asm volatile("cp.async.cg.shared.global [%0], [%1], 16;" :: "r"(dst), "l"(src));
}
__device__ __forceinline__ void cp_commit() {
    asm volatile("cp.async.commit_group;");
}
__device__ __forceinline__ void cp_wait2() {
    asm volatile("cp.async.wait_group 2;");
}

// ---------------------------------------------------------------------------
// Gather. ONE warp per quad (b,k), k in [0,1024). Owns 4 rows / 4 accums:
//   a0 = row 2k      <- cons(k)[w2*od2] + car(4k)[w0*od0] + cdr(4k+1)[w1*od1, skip role 1]
//   a1 = row 2k+1    <- cons(k)[w3*od2] + car(4k+2) + cdr(4k+3) + (k==0: od2*root)
//   b0 = row 2k+2048 <- cons(k+1024)[w2*od2]
//   b1 = row 2k+2049 <- cons(k+1024)[w3*od2]
// Worklist entry int4: {x = (item<<9)|pairbit (byte offset, 512-aligned),
//                       y = c0 (even-row coeff), z = c1 (odd-row coeff), w unused}
// cons items: both coeffs nonzero; car: c1=0; cdr into a1: c0=0, etc.
// 3-stage cp.async pipeline, CHUNK=2, wait_group 2: each chunk is in flight
// two full iterations before its wait.
// ---------------------------------------------------------------------------
#define WPB 8          // warps per block
#define CHUNK 2        // rows per pipeline stage
#define STAGES 3
#define WLMAX 96       // P(six Poisson(2) buckets sum > 96) ~ e^-40; hard-clamped

__global__ void __launch_bounds__(256, 5) gather_kernel(
    const float* __restrict__ mem,       // (N, F)
    const float* __restrict__ arg_w,     // (B, L, 4)
    const float* __restrict__ root,      // (B, F)
    const float* __restrict__ op_dist,   // (B, 3)
    float* __restrict__ out)             // (B, R, F)
{
    __shared__ float  s_awb[LL * 4];                   // 2KB: arg_w[b]
    __shared__ int4   s_wl[WPB][WLMAX];                // 12KB worklist
    __shared__ float4 s_rows[WPB][STAGES][CHUNK][32];  // 24KB staging

    int q = blockIdx.x * WPB + (threadIdx.x >> 5);     // quad [0, 32768)
    const int lane = threadIdx.x & 31;
    const int wid  = (threadIdx.x >> 5);
    const int b = q >> 10;
    const int k = q & 1023;
    const int base = b * RR;

    // cooperative stage of arg_w[b] (batch uniform across the block)
    {
        const float* awg = arg_w + ((size_t)b << 9);
        s_awb[threadIdx.x]       = awg[threadIdx.x];
        s_awb[threadIdx.x + 256] = awg[threadIdx.x + 256];
    }

    const float od0 = op_dist[b * 3 + 0];
    const float od1 = op_dist[b * 3 + 1];
    const float od2 = op_dist[b * 3 + 2];

    const int bk_ch = base + k;            // cons heavy (rows 2k, 2k+1)
    const int bk_cl = base + k + 1024;     // cons light (rows 2k+2048, 2k+2049)
    const int bk_c  = base + 4 * k;        // car0, cdr0, car1, cdr1

    // counts + entries, all issued together (entries unconditional; the array
    // is always-valid memory and garbage lanes are never consumed)
    int  cch_r = g_count[bk_ch];
    int  ccl_r = g_count[bk_cl];
    int4 cc4   = *(const int4*)&g_count[bk_c];
    int e_ch = g_bucket[bk_ch * CAP + lane];
    int e_cl = g_bucket[bk_cl * CAP + lane];
    int e_r0 = g_bucket[(bk_c + 0) * CAP + lane];
    int e_r1 = g_bucket[(bk_c + 1) * CAP + lane];
    int e_r2 = g_bucket[(bk_c + 2) * CAP + lane];
    int e_r3 = g_bucket[(bk_c + 3) * CAP + lane];

    int cch = min(cch_r, CAP);
    int ccl = min(ccl_r, CAP);
    int c0n = min(cc4.x, CAP);
    int c1n = min(cc4.y, CAP);
    int c2n = min(cc4.z, CAP);
    int c3n = min(cc4.w, CAP);
    if (k == 0) c1n = 0;                   // role 1 never contributes via cdr

    __syncthreads();                       // s_awb ready

    // per-lane coefficients from smem
    float2 wch = *(const float2*)&s_awb[(((e_ch >> 18) & 127) << 2) + 2]; // w2,w3
    float2 wcl = *(const float2*)&s_awb[(((e_cl >> 18) & 127) << 2) + 2];
    float cw0 = od0 * s_awb[(((e_r0 >> 18) & 127) << 2) + 0];
    float cw1 = od1 * s_awb[(((e_r1 >> 18) & 127) << 2) + 1];
    float cw2 = od0 * s_awb[(((e_r2 >> 18) & 127) << 2) + 0];
    float cw3 = od1 * s_awb[(((e_r3 >> 18) & 127) << 2) + 1];

    // build worklist: [cons_h | cons_l | car0 | cdr0 | car1 | cdr1]
    // entry.x carries the byte offset of the mem row (item*512), pairbit in bit 0
    int p1 = cch, p2 = p1 + ccl, p3 = p2 + c0n, p4 = p3 + c1n, p5 = p4 + c2n;
    int T = min(p5 + c3n, WLMAX);
    {
        int i0 = lane, i1 = p1 + lane, i2 = p2 + lane;
        int i3 = p3 + lane, i4 = p4 + lane, i5 = p5 + lane;
        if (lane < cch && i0 < WLMAX)
            s_wl[wid][i0] = make_int4(((e_ch & 0x3FFFF) << 9) | 0,
                                      __float_as_int(od2 * wch.x),
                                      __float_as_int(od2 * wch.y), 0);
        if (lane < ccl && i1 < WLMAX)
            s_wl[wid][i1] = make_int4(((e_cl & 0x3FFFF) << 9) | 1,
                                      __float_as_int(od2 * wcl.x),
                                      __float_as_int(od2 * wcl.y), 0);
        if (lane < c0n && i2 < WLMAX)
            s_wl[wid][i2] = make_int4(((e_r0 & 0x3FFFF) << 9),
                                      __float_as_int(cw0), 0, 0);
        if (lane < c1n && i3 < WLMAX)
            s_wl[wid][i3] = make_int4(((e_r1 & 0x3FFFF) << 9),
                                      __float_as_int(cw1), 0, 0);
        if (lane < c2n && i4 < WLMAX)
            s_wl[wid][i4] = make_int4(((e_r2 & 0x3FFFF) << 9),
                                      0, __float_as_int(cw2), 0);
        if (lane < c3n && i5 < WLMAX)
            s_wl[wid][i5] = make_int4(((e_r3 & 0x3FFFF) << 9),
                                      0, __float_as_int(cw3), 0);
    }
    __syncwarp();

    float4 a0 = make_float4(0.f, 0.f, 0.f, 0.f);
    float4 a1 = make_float4(0.f, 0.f, 0.f, 0.f);
    float4 b0 = make_float4(0.f, 0.f, 0.f, 0.f);
    float4 b1 = make_float4(0.f, 0.f, 0.f, 0.f);

    const char* memc = (const char*)mem;
    const int lane16 = lane << 4;
    const int nc = (T + CHUNK - 1) / CHUNK;

    // preload chunks 0 and 1 (commit both groups unconditionally)
#pragma unroll
    for (int p = 0; p < 2; p++) {
#pragma unroll
        for (int u = 0; u < CHUNK; u++) {
            int idx = p * CHUNK + u;
            if (idx < T) {
                int off = s_wl[wid][idx].x & ~1;          // LDS.32
                cp_async16(smem_u32(&s_rows[wid][p][u][lane]), memc + off + lane16);
            }
        }
        cp_commit();
    }

    int st_c = 0;                                          // consume stage
    int st_i = 2;                                          // issue stage
    for (int c = 0; c < nc; c++) {
        int cs2 = (c + 2) * CHUNK;
#pragma unroll
        for (int u = 0; u < CHUNK; u++) {
            int idx = cs2 + u;
            if (idx < T) {
                int off = s_wl[wid][idx].x & ~1;
                cp_async16(smem_u32(&s_rows[wid][st_i][u][lane]), memc + off + lane16);
            }
        }
        cp_commit();
        cp_wait2();                                        // chunk c ready
        int cs = c * CHUNK;
#pragma unroll
        for (int u = 0; u < CHUNK; u++) {
            int idx = cs + u;
            if (idx < T) {
                int4 wl = s_wl[wid][idx];                  // one LDS.128 (broadcast)
                float4 m = s_rows[wid][st_c][u][lane];     // one LDS.128
                float cE = __int_as_float(wl.y);
                float cO = __int_as_float(wl.z);
                if (wl.x & 1) {
                    b0.x += cE * m.x; b0.y += cE * m.y; b0.z += cE * m.z; b0.w += cE * m.w;
                    b1.x += cO * m.x; b1.y += cO * m.y; b1.z += cO * m.z; b1.w += cO * m.w;
                } else {
                    a0.x += cE * m.x; a0.y += cE * m.y; a0.z += cE * m.z; a0.w += cE * m.w;
                    a1.x += cO * m.x; a1.y += cO * m.y; a1.z += cO * m.z; a1.w += cO * m.w;
                }
            }
        }
        st_c = (st_c == STAGES - 1) ? 0 : st_c + 1;
        st_i = (st_i == STAGES - 1) ? 0 : st_i + 1;
    }

    if (k == 0) {                          // row 1 += od2 * root_filler[b]
        float4 rf = ((const float4*)(root + ((size_t)b << 7)))[lane];
        a1.x += od2 * rf.x; a1.y += od2 * rf.y; a1.z += od2 * rf.z; a1.w += od2 * rf.w;
    }

    float* oh = out + ((size_t)base + 2 * (size_t)k) * FF;
    ((float4*)oh)[lane]        = a0;                    // row 2k
    ((float4*)(oh + FF))[lane] = a1;                    // row 2k+1
    float* ol = oh + (size_t)2048 * FF;
    ((float4*)ol)[lane]        = b0;                    // row 2k+2048
    ((float4*)(ol + FF))[lane] = b1;                    // row 2k+2049
}

// ---------------------------------------------------------------------------
extern "C" void kernel_launch(void* const* d_in, const int* in_sizes, int n_in,
                              void* d_out, int out_size) {
    const float* mem     = (const float*)d_in[0];
    const float* arg_w   = (const float*)d_in[1];
    const float* root    = (const float*)d_in[2];
    const float* op_dist = (const float*)d_in[3];
    const int*   batch_i = (const int*)d_in[4];
    const int*   slot_i  = (const int*)d_in[5];
    const int*   role_i  = (const int*)d_in[6];
    float* out = (float*)d_out;

    void* cnt_ptr = nullptr;
    cudaGetSymbolAddress(&cnt_ptr, g_count);
    cudaMemsetAsync(cnt_ptr, 0, sizeof(int) * BB * RR, 0);

    build_buckets_kernel<<<(NITEMS / 4 + 255) / 256, 256>>>(
        (const int4*)batch_i, (const int4*)slot_i, (const int4*)role_i);

    const int nquads = BB * 1024;                  // 32768
    gather_kernel<<<nquads / WPB, 256>>>(mem, arg_w, root, op_dist, out);
}